// round 1
// baseline (speedup 1.0000x reference)
#include <cuda_runtime.h>
#include <math.h>

#define NN    4096
#define DIN   512
#define DD    128
#define NG    16
#define NPG   256
#define RSCALE 0.08838834764831843f   // 1/sqrt(128)

// Scratch for q, k, v projections (device globals: allocation-free)
__device__ float g_q[NN * DD];
__device__ float g_k[NN * DD];
__device__ float g_v[NN * DD];

// ---------- f32x2 packed-FMA helpers (FFMA2: 2x fp32 throughput) ----------
static __device__ __forceinline__ unsigned long long pack2(float x, float y) {
    unsigned long long r;
    asm("mov.b64 %0, {%1,%2};" : "=l"(r) : "f"(x), "f"(y));
    return r;
}
static __device__ __forceinline__ void fma2(unsigned long long& c,
                                            unsigned long long a,
                                            unsigned long long b) {
    asm("fma.rn.f32x2 %0, %1, %2, %3;" : "=l"(c) : "l"(a), "l"(b), "l"(c));
}
static __device__ __forceinline__ float2 unpack2(unsigned long long v) {
    float2 f;
    asm("mov.b64 {%0,%1}, %2;" : "=f"(f.x), "=f"(f.y) : "l"(v));
    return f;
}

// =====================================================================
// Kernel 1: QKV projection.  y = x @ W^T + bias  (x[4096,512], W[128,512])
// grid (128, 1, 3): blockIdx.x = M tile (32 rows), blockIdx.z = q/k/v
// block 256 = 16x16; per-thread micro-tile 2 rows x 8 cols, f32x2 FMA.
// =====================================================================
__global__ void __launch_bounds__(256) qkv_kernel(
    const float* __restrict__ x,
    const float* __restrict__ Wq, const float* __restrict__ Wk, const float* __restrict__ Wv,
    const float* __restrict__ bq, const float* __restrict__ bk, const float* __restrict__ bv)
{
    __shared__ float xs[32 * 33];    // [row][k] pad 33
    __shared__ float ws[32 * 132];   // [k][col] pad 132 (transposed W tile)

    const int t  = threadIdx.x;
    const int tx = t & 15, ty = t >> 4;
    const int m0 = blockIdx.x * 32;
    const int z  = blockIdx.z;

    const float* W    = (z == 0) ? Wq : ((z == 1) ? Wk : Wv);
    const float* bias = (z == 0) ? bq : ((z == 1) ? bk : bv);
    float* out        = (z == 0) ? g_q : ((z == 1) ? g_k : g_v);

    unsigned long long acc[2][4];
#pragma unroll
    for (int r = 0; r < 2; r++)
#pragma unroll
        for (int p = 0; p < 4; p++) acc[r][p] = 0ull;

    const int xr = t >> 3;               // 0..31
    const int xk = (t & 7) * 4;          // 0..28
    const int wj = (t >> 5) * 4 + ((t & 31) >> 3);  // 0..31 (add p*32)
    const int wk = (t & 7) * 4;          // 0..28

    for (int kt = 0; kt < DIN; kt += 32) {
        // stage global loads in registers
        float4 xv = *(const float4*)(x + (m0 + xr) * DIN + kt + xk);
        float4 wv[4];
#pragma unroll
        for (int p = 0; p < 4; p++)
            wv[p] = *(const float4*)(W + (p * 32 + wj) * DIN + kt + wk);

        __syncthreads();   // previous iteration's compute done
        xs[xr * 33 + xk + 0] = xv.x;
        xs[xr * 33 + xk + 1] = xv.y;
        xs[xr * 33 + xk + 2] = xv.z;
        xs[xr * 33 + xk + 3] = xv.w;
#pragma unroll
        for (int p = 0; p < 4; p++) {
            int j = p * 32 + wj;
            ws[(wk + 0) * 132 + j] = wv[p].x;
            ws[(wk + 1) * 132 + j] = wv[p].y;
            ws[(wk + 2) * 132 + j] = wv[p].z;
            ws[(wk + 3) * 132 + j] = wv[p].w;
        }
        __syncthreads();

#pragma unroll
        for (int kk = 0; kk < 32; kk++) {
            float a0 = xs[(ty * 2) * 33 + kk];
            float a1 = xs[(ty * 2 + 1) * 33 + kk];
            float4 b0 = *(const float4*)(ws + kk * 132 + tx * 8);
            float4 b1 = *(const float4*)(ws + kk * 132 + tx * 8 + 4);
            unsigned long long a20 = pack2(a0, a0);
            unsigned long long a21 = pack2(a1, a1);
            unsigned long long bb0 = pack2(b0.x, b0.y);
            unsigned long long bb1 = pack2(b0.z, b0.w);
            unsigned long long bb2 = pack2(b1.x, b1.y);
            unsigned long long bb3 = pack2(b1.z, b1.w);
            fma2(acc[0][0], a20, bb0); fma2(acc[0][1], a20, bb1);
            fma2(acc[0][2], a20, bb2); fma2(acc[0][3], a20, bb3);
            fma2(acc[1][0], a21, bb0); fma2(acc[1][1], a21, bb1);
            fma2(acc[1][2], a21, bb2); fma2(acc[1][3], a21, bb3);
        }
    }

    // epilogue: add bias, store
    float4 bias0 = *(const float4*)(bias + tx * 8);
    float4 bias1 = *(const float4*)(bias + tx * 8 + 4);
#pragma unroll
    for (int r = 0; r < 2; r++) {
        float2 c0 = unpack2(acc[r][0]);
        float2 c1 = unpack2(acc[r][1]);
        float2 c2 = unpack2(acc[r][2]);
        float2 c3 = unpack2(acc[r][3]);
        float4 o0 = make_float4(c0.x + bias0.x, c0.y + bias0.y, c1.x + bias0.z, c1.y + bias0.w);
        float4 o1 = make_float4(c2.x + bias1.x, c2.y + bias1.y, c3.x + bias1.z, c3.y + bias1.w);
        int row = m0 + ty * 2 + r;
        *(float4*)(out + row * DD + tx * 8)     = o0;
        *(float4*)(out + row * DD + tx * 8 + 4) = o1;
    }
}

// =====================================================================
// Kernel 2: block-diagonal attention, one CTA = 32 query rows of a graph.
// grid (8, 16): blockIdx.x = row tile, blockIdx.y = graph. block 256.
// S = Q K^T / sqrt(128) + b + c (masked); softmax; O = P V / rowsum.
// =====================================================================
#define ATTN_SMEM_FLOATS (32 * 132 + 64 * 132 + 32 * 257 + 32)
#define ATTN_SMEM_BYTES  (ATTN_SMEM_FLOATS * 4)

__global__ void __launch_bounds__(256) attn_kernel(
    const float* __restrict__ bmat,
    const float* __restrict__ cmat,
    const int*   __restrict__ mask,
    float* __restrict__ out)
{
    extern __shared__ float smem[];
    float* qs   = smem;                       // [32][132]
    float* ks   = smem + 32 * 132;            // [64][132] (reused for V)
    float* ps   = ks + 64 * 132;              // [32][257]
    float* rsum = ps + 32 * 257;              // [32]

    const int t  = threadIdx.x;
    const int tx = t & 15, ty = t >> 4;
    const int g     = blockIdx.y;
    const int nbase = g * NPG + blockIdx.x * 32;  // first query row (global)
    const int kbase = g * NPG;                    // first key row (global)

    // load Q tile [32][128]
    {
        int r = t >> 3, dp = (t & 7) * 16;
#pragma unroll
        for (int i = 0; i < 4; i++) {
            float4 v = *(const float4*)(g_q + (nbase + r) * DD + dp + i * 4);
            *(float4*)(qs + r * 132 + dp + i * 4) = v;
        }
    }

    float s[2][16];
#pragma unroll
    for (int r = 0; r < 2; r++)
#pragma unroll
        for (int i = 0; i < 16; i++) s[r][i] = 0.f;

    const int lr = t >> 2, ldp = (t & 3) * 32;  // K/V chunk loader

    // ---- Phase 1: scores over 4 chunks of 64 keys ----
#pragma unroll
    for (int ch = 0; ch < 4; ch++) {
        __syncthreads();
#pragma unroll
        for (int i = 0; i < 8; i++) {
            float4 v = *(const float4*)(g_k + (kbase + ch * 64 + lr) * DD + ldp + i * 4);
            *(float4*)(ks + lr * 132 + ldp + i * 4) = v;
        }
        __syncthreads();
#pragma unroll 8
        for (int d = 0; d < DD; d += 4) {
            float4 q0 = *(const float4*)(qs + (ty * 2) * 132 + d);
            float4 q1 = *(const float4*)(qs + (ty * 2 + 1) * 132 + d);
#pragma unroll
            for (int cc = 0; cc < 4; cc++) {
                float4 k4 = *(const float4*)(ks + (cc * 16 + tx) * 132 + d);
                s[0][ch * 4 + cc] += q0.x * k4.x + q0.y * k4.y + q0.z * k4.z + q0.w * k4.w;
                s[1][ch * 4 + cc] += q1.x * k4.x + q1.y * k4.y + q1.z * k4.z + q1.w * k4.w;
            }
        }
    }

    // ---- bias + mask + softmax (only block-diagonal of b/c/mask is read) ----
#pragma unroll
    for (int r = 0; r < 2; r++) {
        const int grow = nbase + ty * 2 + r;
        float mx = -1e30f;
#pragma unroll
        for (int i = 0; i < 16; i++) {
            int gcol = kbase + (i >> 2) * 64 + (i & 3) * 16 + tx;
            int idx = grow * NN + gcol;
            float v = (mask[idx] != 0)
                          ? (s[r][i] * RSCALE + bmat[idx] + cmat[idx])
                          : -1e30f;
            s[r][i] = v;
            mx = fmaxf(mx, v);
        }
#pragma unroll
        for (int o = 8; o >= 1; o >>= 1)
            mx = fmaxf(mx, __shfl_xor_sync(0xffffffffu, mx, o));
        float sum = 0.f;
#pragma unroll
        for (int i = 0; i < 16; i++) {
            float e = __expf(s[r][i] - mx);
            s[r][i] = e;
            sum += e;
        }
#pragma unroll
        for (int o = 8; o >= 1; o >>= 1)
            sum += __shfl_xor_sync(0xffffffffu, sum, o);
#pragma unroll
        for (int i = 0; i < 16; i++)
            ps[(ty * 2 + r) * 257 + (i >> 2) * 64 + (i & 3) * 16 + tx] = s[r][i];
        if (tx == 0) rsum[ty * 2 + r] = sum;
    }

    // ---- Phase 2: O = P @ V ----
    float o0[8], o1[8];
#pragma unroll
    for (int j = 0; j < 8; j++) { o0[j] = 0.f; o1[j] = 0.f; }

    for (int ch = 0; ch < 4; ch++) {
        __syncthreads();  // ps written / previous ks reads done
#pragma unroll
        for (int i = 0; i < 8; i++) {
            float4 v = *(const float4*)(g_v + (kbase + ch * 64 + lr) * DD + ldp + i * 4);
            *(float4*)(ks + lr * 132 + ldp + i * 4) = v;
        }
        __syncthreads();
#pragma unroll 4
        for (int cl = 0; cl < 64; cl++) {
            float p0 = ps[(ty * 2) * 257 + ch * 64 + cl];
            float p1 = ps[(ty * 2 + 1) * 257 + ch * 64 + cl];
            float4 va = *(const float4*)(ks + cl * 132 + tx * 8);
            float4 vb = *(const float4*)(ks + cl * 132 + tx * 8 + 4);
            o0[0] += p0 * va.x; o0[1] += p0 * va.y; o0[2] += p0 * va.z; o0[3] += p0 * va.w;
            o0[4] += p0 * vb.x; o0[5] += p0 * vb.y; o0[6] += p0 * vb.z; o0[7] += p0 * vb.w;
            o1[0] += p1 * va.x; o1[1] += p1 * va.y; o1[2] += p1 * va.z; o1[3] += p1 * va.w;
            o1[4] += p1 * vb.x; o1[5] += p1 * vb.y; o1[6] += p1 * vb.z; o1[7] += p1 * vb.w;
        }
    }

    float inv0 = 1.0f / rsum[ty * 2];
    float inv1 = 1.0f / rsum[ty * 2 + 1];
    int row0 = nbase + ty * 2;
    *(float4*)(out + row0 * DD + tx * 8) =
        make_float4(o0[0] * inv0, o0[1] * inv0, o0[2] * inv0, o0[3] * inv0);
    *(float4*)(out + row0 * DD + tx * 8 + 4) =
        make_float4(o0[4] * inv0, o0[5] * inv0, o0[6] * inv0, o0[7] * inv0);
    *(float4*)(out + (row0 + 1) * DD + tx * 8) =
        make_float4(o1[0] * inv1, o1[1] * inv1, o1[2] * inv1, o1[3] * inv1);
    *(float4*)(out + (row0 + 1) * DD + tx * 8 + 4) =
        make_float4(o1[4] * inv1, o1[5] * inv1, o1[6] * inv1, o1[7] * inv1);
}

// =====================================================================
extern "C" void kernel_launch(void* const* d_in, const int* in_sizes, int n_in,
                              void* d_out, int out_size)
{
    const float* x    = (const float*)d_in[0];
    const float* bmat = (const float*)d_in[1];
    const float* cmat = (const float*)d_in[2];
    // d_in[3] = ptr (graph layout is uniform: NPG = 256; unused)
    const int*   mask = (const int*)d_in[4];
    const float* Wq   = (const float*)d_in[5];
    const float* bq   = (const float*)d_in[6];
    const float* Wk   = (const float*)d_in[7];
    const float* bk   = (const float*)d_in[8];
    const float* Wv   = (const float*)d_in[9];
    const float* bv   = (const float*)d_in[10];
    float* out = (float*)d_out;

    cudaFuncSetAttribute(attn_kernel, cudaFuncAttributeMaxDynamicSharedMemorySize,
                         ATTN_SMEM_BYTES);

    qkv_kernel<<<dim3(128, 1, 3), 256>>>(x, Wq, Wk, Wv, bq, bk, bv);
    attn_kernel<<<dim3(8, 16), 256, ATTN_SMEM_BYTES>>>(bmat, cmat, mask, out);
}

// round 8
// speedup vs baseline: 2.0436x; 2.0436x over previous
#include <cuda_runtime.h>
#include <cuda_bf16.h>
#include <cstdint>
#include <math.h>

#define NN    4096
#define DIN   512
#define DD    128
#define NG    16
#define NPG   256
#define RSCALE 0.08838834764831843f   // 1/sqrt(128)

// ---------------- device scratch (allocation-free) ----------------
__device__ float g_q[NN * DD];
__device__ float g_k[NN * DD];
__device__ float g_v[NN * DD];
__device__ __nv_bfloat16 g_xh[NN * DIN];
__device__ __nv_bfloat16 g_xl[NN * DIN];
__device__ __nv_bfloat16 g_wh[3 * DD * DIN];
__device__ __nv_bfloat16 g_wl[3 * DD * DIN];

// ---------------- baseline-PTX tensor-core helpers ----------------
static __device__ __forceinline__ uint32_t smem_u32(const void* p) {
    uint32_t a;
    asm("{ .reg .u64 t; cvta.to.shared.u64 t, %1; cvt.u32.u64 %0, t; }" : "=r"(a) : "l"(p));
    return a;
}
static __device__ __forceinline__ void ldsm_x4(uint32_t addr, uint32_t* r) {
    asm volatile("ldmatrix.sync.aligned.m8n8.x4.shared.b16 {%0,%1,%2,%3}, [%4];"
                 : "=r"(r[0]), "=r"(r[1]), "=r"(r[2]), "=r"(r[3]) : "r"(addr));
}
static __device__ __forceinline__ void mma_bf16(float* c, const uint32_t* a, const uint32_t* b) {
    asm volatile(
        "mma.sync.aligned.m16n8k16.row.col.f32.bf16.bf16.f32 "
        "{%0,%1,%2,%3}, {%4,%5,%6,%7}, {%8,%9}, {%0,%1,%2,%3};"
        : "+f"(c[0]), "+f"(c[1]), "+f"(c[2]), "+f"(c[3])
        : "r"(a[0]), "r"(a[1]), "r"(a[2]), "r"(a[3]), "r"(b[0]), "r"(b[1]));
}

// =====================================================================
// Kernel 0a: split-convert x -> (xh, xl) bf16
// =====================================================================
__global__ void __launch_bounds__(256) convert_x_kernel(const float* __restrict__ x)
{
    int i = blockIdx.x * 256 + threadIdx.x;     // float4 index
    float4 v = ((const float4*)x)[i];
    float f[4] = {v.x, v.y, v.z, v.w};
    unsigned short hs[4], ls[4];
#pragma unroll
    for (int j = 0; j < 4; j++) {
        __nv_bfloat16 h = __float2bfloat16(f[j]);
        float lo = f[j] - __bfloat162float(h);
        __nv_bfloat16 l = __float2bfloat16(lo);
        hs[j] = __bfloat16_as_ushort(h);
        ls[j] = __bfloat16_as_ushort(l);
    }
    uint2 hp, lp;
    hp.x = (uint32_t)hs[0] | ((uint32_t)hs[1] << 16);
    hp.y = (uint32_t)hs[2] | ((uint32_t)hs[3] << 16);
    lp.x = (uint32_t)ls[0] | ((uint32_t)ls[1] << 16);
    lp.y = (uint32_t)ls[2] | ((uint32_t)ls[3] << 16);
    ((uint2*)g_xh)[i] = hp;
    ((uint2*)g_xl)[i] = lp;
}

// =====================================================================
// Kernel 0b: split-convert Wq|Wk|Wv -> (g_wh, g_wl) [384, 512]
// =====================================================================
__global__ void __launch_bounds__(256) convert_w_kernel(
    const float* __restrict__ Wq, const float* __restrict__ Wk, const float* __restrict__ Wv)
{
    int i = blockIdx.x * 256 + threadIdx.x;     // float4 index
    int fidx = i * 4;
    int row = fidx >> 9;           // 0..383
    int col = fidx & 511;
    const float* src = (row < 128) ? (Wq + row * 512)
                     : (row < 256) ? (Wk + (row - 128) * 512)
                                   : (Wv + (row - 256) * 512);
    float4 v = *(const float4*)(src + col);
    float f[4] = {v.x, v.y, v.z, v.w};
    unsigned short hs[4], ls[4];
#pragma unroll
    for (int j = 0; j < 4; j++) {
        __nv_bfloat16 h = __float2bfloat16(f[j]);
        float lo = f[j] - __bfloat162float(h);
        __nv_bfloat16 l = __float2bfloat16(lo);
        hs[j] = __bfloat16_as_ushort(h);
        ls[j] = __bfloat16_as_ushort(l);
    }
    uint2 hp, lp;
    hp.x = (uint32_t)hs[0] | ((uint32_t)hs[1] << 16);
    hp.y = (uint32_t)hs[2] | ((uint32_t)hs[3] << 16);
    lp.x = (uint32_t)ls[0] | ((uint32_t)ls[1] << 16);
    lp.y = (uint32_t)ls[2] | ((uint32_t)ls[3] << 16);
    ((uint2*)g_wh)[i] = hp;
    ((uint2*)g_wl)[i] = lp;
}

// =====================================================================
// Kernel 1: QKV projection via mma.sync (bf16 split, 3 accumulating passes)
// grid (128, 3): x = M tile (32 rows), y = q/k/v. block 128 (4 warps).
// CTA tile 32x128, K chunks of 64; warp tile 16x64 (2m x 2n warps).
// =====================================================================
__global__ void __launch_bounds__(128) qkv_mma_kernel(
    const float* __restrict__ bq, const float* __restrict__ bk, const float* __restrict__ bv)
{
    __shared__ __align__(16) __nv_bfloat16 sAh[32 * 72];
    __shared__ __align__(16) __nv_bfloat16 sAl[32 * 72];
    __shared__ __align__(16) __nv_bfloat16 sBh[128 * 72];
    __shared__ __align__(16) __nv_bfloat16 sBl[128 * 72];

    const int t    = threadIdx.x;
    const int lane = t & 31;
    const int wid  = t >> 5;
    const int m0   = blockIdx.x * 32;
    const int z    = blockIdx.y;

    const __nv_bfloat16* Wh = g_wh + z * DD * DIN;
    const __nv_bfloat16* Wl = g_wl + z * DD * DIN;
    const float* bias = (z == 0) ? bq : ((z == 1) ? bk : bv);
    float* out        = (z == 0) ? g_q : ((z == 1) ? g_k : g_v);

    const int wm = wid & 1;        // m-tile within CTA (0/1)
    const int wn = wid >> 1;       // n-half (0/1), 64 cols each

    float acc[8][4];
#pragma unroll
    for (int nt = 0; nt < 8; nt++)
#pragma unroll
        for (int j = 0; j < 4; j++) acc[nt][j] = 0.f;

    // ldmatrix per-lane base addresses (bytes)
    // A (non-trans): lanes 0-15 -> rows 0..15 at k+0; lanes 16-31 -> rows at k+8
    const uint32_t aoff = (uint32_t)(((wm * 16 + (lane & 15)) * 72 + ((lane >> 4) * 8)) * 2);
    const uint32_t aAh = smem_u32(sAh) + aoff;
    const uint32_t aAl = smem_u32(sAl) + aoff;
    // B (non-trans on [n][k] = col-major KxN): lanes 0-7 -> n rows 0..7 at k+0,
    // lanes 8-15 -> k+8, lanes 16-23 -> k+16, lanes 24-31 -> k+24
    const uint32_t boff = (uint32_t)((((lane & 7)) * 72 + ((lane >> 3) * 8)) * 2);
    const uint32_t aBh = smem_u32(sBh) + boff;
    const uint32_t aBl = smem_u32(sBl) + boff;

    for (int ch = 0; ch < 8; ch++) {
        __syncthreads();
        // stage A tiles: 32 rows x 64 bf16 (hi & lo)
#pragma unroll
        for (int j = 0; j < 2; j++) {
            int c   = t + j * 128;
            int row = c >> 3, o8 = (c & 7) * 8;
            int gsrc = (m0 + row) * DIN + ch * 64 + o8;
            *(uint4*)(sAh + row * 72 + o8) = *(const uint4*)(g_xh + gsrc);
            *(uint4*)(sAl + row * 72 + o8) = *(const uint4*)(g_xl + gsrc);
        }
        // stage B tiles: 128 rows x 64 bf16 (hi & lo)
#pragma unroll
        for (int j = 0; j < 8; j++) {
            int c   = t + j * 128;
            int row = c >> 3, o8 = (c & 7) * 8;
            int gsrc = row * DIN + ch * 64 + o8;
            *(uint4*)(sBh + row * 72 + o8) = *(const uint4*)(Wh + gsrc);
            *(uint4*)(sBl + row * 72 + o8) = *(const uint4*)(Wl + gsrc);
        }
        __syncthreads();

        // A fragments for all 4 k-steps of this chunk
        uint32_t ah[4][4], al[4][4];
#pragma unroll
        for (int ks = 0; ks < 4; ks++) {
            ldsm_x4(aAh + ks * 32, ah[ks]);
            ldsm_x4(aAl + ks * 32, al[ks]);
        }

#pragma unroll
        for (int nt = 0; nt < 8; nt++) {
            uint32_t bofs = (uint32_t)((wn * 64 + nt * 8) * 144);
#pragma unroll
            for (int kp = 0; kp < 2; kp++) {
                uint32_t bh[4], bl[4];
                ldsm_x4(aBh + bofs + kp * 64, bh);   // non-trans: fragment pairs run along k
                ldsm_x4(aBl + bofs + kp * 64, bl);
                // k-step kp*2 : b regs {0,1};  k-step kp*2+1 : b regs {2,3}
                mma_bf16(acc[nt], ah[kp * 2],     bh);
                mma_bf16(acc[nt], ah[kp * 2],     bl);
                mma_bf16(acc[nt], al[kp * 2],     bh);
                mma_bf16(acc[nt], ah[kp * 2 + 1], bh + 2);
                mma_bf16(acc[nt], ah[kp * 2 + 1], bl + 2);
                mma_bf16(acc[nt], al[kp * 2 + 1], bh + 2);
            }
        }
    }

    // epilogue: acc -> out (+bias). lane: g = lane>>2 (row), tq = lane&3 (col pair)
    const int g  = lane >> 2;
    const int tq = lane & 3;
    const int row = m0 + wm * 16 + g;
#pragma unroll
    for (int nt = 0; nt < 8; nt++) {
        int col = wn * 64 + nt * 8 + tq * 2;
        float2 bz = *(const float2*)(bias + col);
        *(float2*)(out + row * DD + col) =
            make_float2(acc[nt][0] + bz.x, acc[nt][1] + bz.y);
        *(float2*)(out + (row + 8) * DD + col) =
            make_float2(acc[nt][2] + bz.x, acc[nt][3] + bz.y);
    }
}

// =====================================================================
// Kernel 2: block-diagonal attention, one CTA = 16 query rows of a graph.
// grid (16, 16): blockIdx.x = row tile, blockIdx.y = graph. block 128.
// =====================================================================
#define ATTN_SMEM_FLOATS (16 * 132 + 64 * 132 + 16 * 257 + 16)
#define ATTN_SMEM_BYTES  (ATTN_SMEM_FLOATS * 4)

__global__ void __launch_bounds__(128) attn_kernel(
    const float* __restrict__ bmat,
    const float* __restrict__ cmat,
    const int*   __restrict__ mask,
    float* __restrict__ out)
{
    extern __shared__ float asmem[];
    float* qs   = asmem;                      // [16][132]
    float* ks   = asmem + 16 * 132;           // [64][132] (reused for V)
    float* ps   = ks + 64 * 132;              // [16][257]
    float* rsum = ps + 16 * 257;              // [16]

    const int t  = threadIdx.x;
    const int tx = t & 15, ty = t >> 4;       // ty 0..7
    const int g     = blockIdx.y;
    const int nbase = g * NPG + blockIdx.x * 16;  // first query row (global)
    const int kbase = g * NPG;                    // first key row (global)

    // load Q tile [16][128]
    {
        int r = t >> 3, dp = (t & 7) * 16;
#pragma unroll
        for (int i = 0; i < 4; i++) {
            float4 v = *(const float4*)(g_q + (nbase + r) * DD + dp + i * 4);
            *(float4*)(qs + r * 132 + dp + i * 4) = v;
        }
    }

    float s[2][16];
#pragma unroll
    for (int r = 0; r < 2; r++)
#pragma unroll
        for (int i = 0; i < 16; i++) s[r][i] = 0.f;

    const int lr = t >> 1, ldp = (t & 1) * 64;  // K/V chunk loader (64 rows)

    // ---- Phase 1: scores over 4 chunks of 64 keys ----
#pragma unroll
    for (int ch = 0; ch < 4; ch++) {
        __syncthreads();
#pragma unroll
        for (int i = 0; i < 16; i++) {
            float4 v = *(const float4*)(g_k + (kbase + ch * 64 + lr) * DD + ldp + i * 4);
            *(float4*)(ks + lr * 132 + ldp + i * 4) = v;
        }
        __syncthreads();
#pragma unroll 8
        for (int d = 0; d < DD; d += 4) {
            float4 q0 = *(const float4*)(qs + (ty * 2) * 132 + d);
            float4 q1 = *(const float4*)(qs + (ty * 2 + 1) * 132 + d);
#pragma unroll
            for (int cc = 0; cc < 4; cc++) {
                float4 k4 = *(const float4*)(ks + (cc * 16 + tx) * 132 + d);
                s[0][ch * 4 + cc] += q0.x * k4.x + q0.y * k4.y + q0.z * k4.z + q0.w * k4.w;
                s[1][ch * 4 + cc] += q1.x * k4.x + q1.y * k4.y + q1.z * k4.z + q1.w * k4.w;
            }
        }
    }

    // ---- bias + mask + softmax (block-diagonal of b/c/mask only) ----
#pragma unroll
    for (int r = 0; r < 2; r++) {
        const int grow = nbase + ty * 2 + r;
        float mx = -1e30f;
#pragma unroll
        for (int i = 0; i < 16; i++) {
            int gcol = kbase + (i >> 2) * 64 + (i & 3) * 16 + tx;
            int idx = grow * NN + gcol;
            float v = (mask[idx] != 0)
                          ? (s[r][i] * RSCALE + bmat[idx] + cmat[idx])
                          : -1e30f;
            s[r][i] = v;
            mx = fmaxf(mx, v);
        }
#pragma unroll
        for (int o = 8; o >= 1; o >>= 1)
            mx = fmaxf(mx, __shfl_xor_sync(0xffffffffu, mx, o));
        float sum = 0.f;
#pragma unroll
        for (int i = 0; i < 16; i++) {
            float e = __expf(s[r][i] - mx);
            s[r][i] = e;
            sum += e;
        }
#pragma unroll
        for (int o = 8; o >= 1; o >>= 1)
            sum += __shfl_xor_sync(0xffffffffu, sum, o);
#pragma unroll
        for (int i = 0; i < 16; i++)
            ps[(ty * 2 + r) * 257 + (i >> 2) * 64 + (i & 3) * 16 + tx] = s[r][i];
        if (tx == 0) rsum[ty * 2 + r] = sum;
    }

    // ---- Phase 2: O = P @ V ----
    float o0[8], o1[8];
#pragma unroll
    for (int j = 0; j < 8; j++) { o0[j] = 0.f; o1[j] = 0.f; }

    for (int ch = 0; ch < 4; ch++) {
        __syncthreads();
#pragma unroll
        for (int i = 0; i < 16; i++) {
            float4 v = *(const float4*)(g_v + (kbase + ch * 64 + lr) * DD + ldp + i * 4);
            *(float4*)(ks + lr * 132 + ldp + i * 4) = v;
        }
        __syncthreads();
#pragma unroll 4
        for (int cl = 0; cl < 64; cl++) {
            float p0 = ps[(ty * 2) * 257 + ch * 64 + cl];
            float p1 = ps[(ty * 2 + 1) * 257 + ch * 64 + cl];
            float4 va = *(const float4*)(ks + cl * 132 + tx * 8);
            float4 vb = *(const float4*)(ks + cl * 132 + tx * 8 + 4);
            o0[0] += p0 * va.x; o0[1] += p0 * va.y; o0[2] += p0 * va.z; o0[3] += p0 * va.w;
            o0[4] += p0 * vb.x; o0[5] += p0 * vb.y; o0[6] += p0 * vb.z; o0[7] += p0 * vb.w;
            o1[0] += p1 * va.x; o1[1] += p1 * va.y; o1[2] += p1 * va.z; o1[3] += p1 * va.w;
            o1[4] += p1 * vb.x; o1[5] += p1 * vb.y; o1[6] += p1 * vb.z; o1[7] += p1 * vb.w;
        }
    }

    float inv0 = 1.0f / rsum[ty * 2];
    float inv1 = 1.0f / rsum[ty * 2 + 1];
    int row0 = nbase + ty * 2;
    *(float4*)(out + row0 * DD + tx * 8) =
        make_float4(o0[0] * inv0, o0[1] * inv0, o0[2] * inv0, o0[3] * inv0);
    *(float4*)(out + row0 * DD + tx * 8 + 4) =
        make_float4(o0[4] * inv0, o0[5] * inv0, o0[6] * inv0, o0[7] * inv0);
    *(float4*)(out + (row0 + 1) * DD + tx * 8) =
        make_float4(o1[0] * inv1, o1[1] * inv1, o1[2] * inv1, o1[3] * inv1);
    *(float4*)(out + (row0 + 1) * DD + tx * 8 + 4) =
        make_float4(o1[4] * inv1, o1[5] * inv1, o1[6] * inv1, o1[7] * inv1);
}

// =====================================================================
extern "C" void kernel_launch(void* const* d_in, const int* in_sizes, int n_in,
                              void* d_out, int out_size)
{
    const float* x    = (const float*)d_in[0];
    const float* bmat = (const float*)d_in[1];
    const float* cmat = (const float*)d_in[2];
    // d_in[3] = ptr (uniform graph layout: NPG = 256; unused)
    const int*   mask = (const int*)d_in[4];
    const float* Wq   = (const float*)d_in[5];
    const float* bq   = (const float*)d_in[6];
    const float* Wk   = (const float*)d_in[7];
    const float* bk   = (const float*)d_in[8];
    const float* Wv   = (const float*)d_in[9];
    const float* bv   = (const float*)d_in[10];
    float* out = (float*)d_out;

    cudaFuncSetAttribute(attn_kernel, cudaFuncAttributeMaxDynamicSharedMemorySize,
                         ATTN_SMEM_BYTES);

    convert_x_kernel<<<(NN * DIN / 4) / 256, 256>>>(x);
    convert_w_kernel<<<(3 * DD * DIN / 4) / 256, 256>>>(Wq, Wk, Wv);
    qkv_mma_kernel<<<dim3(128, 3), 128>>>(bq, bk, bv);
    attn_kernel<<<dim3(16, 16), 128, ATTN_SMEM_BYTES>>>(bmat, cmat, mask, out);
}

// round 9
// speedup vs baseline: 2.6968x; 1.3197x over previous
#include <cuda_runtime.h>
#include <cuda_bf16.h>
#include <cstdint>
#include <math.h>

#define NN    4096
#define DIN   512
#define DD    128
#define NG    16
#define NPG   256
#define RSCALE 0.08838834764831843f   // 1/sqrt(128)

// ---------------- device scratch (allocation-free) ----------------
__device__ __nv_bfloat16 g_qh[NN * DD];
__device__ __nv_bfloat16 g_ql[NN * DD];
__device__ __nv_bfloat16 g_kh[NN * DD];
__device__ __nv_bfloat16 g_kl[NN * DD];
__device__ __nv_bfloat16 g_vh[NN * DD];
__device__ __nv_bfloat16 g_vl[NN * DD];
__device__ __nv_bfloat16 g_xh[NN * DIN];
__device__ __nv_bfloat16 g_xl[NN * DIN];
__device__ __nv_bfloat16 g_wh[3 * DD * DIN];
__device__ __nv_bfloat16 g_wl[3 * DD * DIN];

// ---------------- baseline-PTX tensor-core helpers ----------------
static __device__ __forceinline__ uint32_t smem_u32(const void* p) {
    uint32_t a;
    asm("{ .reg .u64 t; cvta.to.shared.u64 t, %1; cvt.u32.u64 %0, t; }" : "=r"(a) : "l"(p));
    return a;
}
static __device__ __forceinline__ void ldsm_x4(uint32_t addr, uint32_t* r) {
    asm volatile("ldmatrix.sync.aligned.m8n8.x4.shared.b16 {%0,%1,%2,%3}, [%4];"
                 : "=r"(r[0]), "=r"(r[1]), "=r"(r[2]), "=r"(r[3]) : "r"(addr));
}
static __device__ __forceinline__ void ldsm_x4_t(uint32_t addr, uint32_t* r) {
    asm volatile("ldmatrix.sync.aligned.m8n8.x4.trans.shared.b16 {%0,%1,%2,%3}, [%4];"
                 : "=r"(r[0]), "=r"(r[1]), "=r"(r[2]), "=r"(r[3]) : "r"(addr));
}
static __device__ __forceinline__ void mma_bf16(float* c, const uint32_t* a, const uint32_t* b) {
    asm volatile(
        "mma.sync.aligned.m16n8k16.row.col.f32.bf16.bf16.f32 "
        "{%0,%1,%2,%3}, {%4,%5,%6,%7}, {%8,%9}, {%0,%1,%2,%3};"
        : "+f"(c[0]), "+f"(c[1]), "+f"(c[2]), "+f"(c[3])
        : "r"(a[0]), "r"(a[1]), "r"(a[2]), "r"(a[3]), "r"(b[0]), "r"(b[1]));
}
// pack two floats into split-bf16: returns hi pair, writes lo pair
static __device__ __forceinline__ uint32_t split_pack(float a, float b, uint32_t* lo) {
    __nv_bfloat16 ha = __float2bfloat16(a), hb = __float2bfloat16(b);
    __nv_bfloat16 la = __float2bfloat16(a - __bfloat162float(ha));
    __nv_bfloat16 lb = __float2bfloat16(b - __bfloat162float(hb));
    *lo = (uint32_t)__bfloat16_as_ushort(la) | ((uint32_t)__bfloat16_as_ushort(lb) << 16);
    return (uint32_t)__bfloat16_as_ushort(ha) | ((uint32_t)__bfloat16_as_ushort(hb) << 16);
}

// =====================================================================
// Kernel 0a: split-convert x -> (xh, xl) bf16
// =====================================================================
__global__ void __launch_bounds__(256) convert_x_kernel(const float* __restrict__ x)
{
    int i = blockIdx.x * 256 + threadIdx.x;     // float4 index
    float4 v = ((const float4*)x)[i];
    uint2 hp, lp;
    hp.x = split_pack(v.x, v.y, &lp.x);
    hp.y = split_pack(v.z, v.w, &lp.y);
    ((uint2*)g_xh)[i] = hp;
    ((uint2*)g_xl)[i] = lp;
}

// =====================================================================
// Kernel 0b: split-convert Wq|Wk|Wv -> (g_wh, g_wl) [384, 512]
// =====================================================================
__global__ void __launch_bounds__(256) convert_w_kernel(
    const float* __restrict__ Wq, const float* __restrict__ Wk, const float* __restrict__ Wv)
{
    int i = blockIdx.x * 256 + threadIdx.x;     // float4 index
    int fidx = i * 4;
    int row = fidx >> 9;           // 0..383
    int col = fidx & 511;
    const float* src = (row < 128) ? (Wq + row * 512)
                     : (row < 256) ? (Wk + (row - 128) * 512)
                                   : (Wv + (row - 256) * 512);
    float4 v = *(const float4*)(src + col);
    uint2 hp, lp;
    hp.x = split_pack(v.x, v.y, &lp.x);
    hp.y = split_pack(v.z, v.w, &lp.y);
    ((uint2*)g_wh)[i] = hp;
    ((uint2*)g_wl)[i] = lp;
}

// =====================================================================
// Kernel 1: QKV projection via mma.sync (bf16 split, 3 accumulating passes)
// grid (128, 3): x = M tile (32 rows), y = q/k/v. block 128 (4 warps).
// Epilogue stores split-bf16 (hi/lo) directly for the attention kernel.
// =====================================================================
__global__ void __launch_bounds__(128) qkv_mma_kernel(
    const float* __restrict__ bq, const float* __restrict__ bk, const float* __restrict__ bv)
{
    __shared__ __align__(16) __nv_bfloat16 sAh[32 * 72];
    __shared__ __align__(16) __nv_bfloat16 sAl[32 * 72];
    __shared__ __align__(16) __nv_bfloat16 sBh[128 * 72];
    __shared__ __align__(16) __nv_bfloat16 sBl[128 * 72];

    const int t    = threadIdx.x;
    const int lane = t & 31;
    const int wid  = t >> 5;
    const int m0   = blockIdx.x * 32;
    const int z    = blockIdx.y;

    const __nv_bfloat16* Wh = g_wh + z * DD * DIN;
    const __nv_bfloat16* Wl = g_wl + z * DD * DIN;
    const float* bias = (z == 0) ? bq : ((z == 1) ? bk : bv);
    __nv_bfloat16* outh = (z == 0) ? g_qh : ((z == 1) ? g_kh : g_vh);
    __nv_bfloat16* outl = (z == 0) ? g_ql : ((z == 1) ? g_kl : g_vl);

    const int wm = wid & 1;        // m-tile within CTA (0/1)
    const int wn = wid >> 1;       // n-half (0/1), 64 cols each

    float acc[8][4];
#pragma unroll
    for (int nt = 0; nt < 8; nt++)
#pragma unroll
        for (int j = 0; j < 4; j++) acc[nt][j] = 0.f;

    const uint32_t aoff = (uint32_t)(((wm * 16 + (lane & 15)) * 72 + ((lane >> 4) * 8)) * 2);
    const uint32_t aAh = smem_u32(sAh) + aoff;
    const uint32_t aAl = smem_u32(sAl) + aoff;
    const uint32_t boff = (uint32_t)((((lane & 7)) * 72 + ((lane >> 3) * 8)) * 2);
    const uint32_t aBh = smem_u32(sBh) + boff;
    const uint32_t aBl = smem_u32(sBl) + boff;

    for (int ch = 0; ch < 8; ch++) {
        __syncthreads();
#pragma unroll
        for (int j = 0; j < 2; j++) {
            int c   = t + j * 128;
            int row = c >> 3, o8 = (c & 7) * 8;
            int gsrc = (m0 + row) * DIN + ch * 64 + o8;
            *(uint4*)(sAh + row * 72 + o8) = *(const uint4*)(g_xh + gsrc);
            *(uint4*)(sAl + row * 72 + o8) = *(const uint4*)(g_xl + gsrc);
        }
#pragma unroll
        for (int j = 0; j < 8; j++) {
            int c   = t + j * 128;
            int row = c >> 3, o8 = (c & 7) * 8;
            int gsrc = row * DIN + ch * 64 + o8;
            *(uint4*)(sBh + row * 72 + o8) = *(const uint4*)(Wh + gsrc);
            *(uint4*)(sBl + row * 72 + o8) = *(const uint4*)(Wl + gsrc);
        }
        __syncthreads();

        uint32_t ah[4][4], al[4][4];
#pragma unroll
        for (int ks = 0; ks < 4; ks++) {
            ldsm_x4(aAh + ks * 32, ah[ks]);
            ldsm_x4(aAl + ks * 32, al[ks]);
        }

#pragma unroll
        for (int nt = 0; nt < 8; nt++) {
            uint32_t bofs = (uint32_t)((wn * 64 + nt * 8) * 144);
#pragma unroll
            for (int kp = 0; kp < 2; kp++) {
                uint32_t bh[4], bl[4];
                ldsm_x4(aBh + bofs + kp * 64, bh);
                ldsm_x4(aBl + bofs + kp * 64, bl);
                mma_bf16(acc[nt], ah[kp * 2],     bh);
                mma_bf16(acc[nt], ah[kp * 2],     bl);
                mma_bf16(acc[nt], al[kp * 2],     bh);
                mma_bf16(acc[nt], ah[kp * 2 + 1], bh + 2);
                mma_bf16(acc[nt], ah[kp * 2 + 1], bl + 2);
                mma_bf16(acc[nt], al[kp * 2 + 1], bh + 2);
            }
        }
    }

    // epilogue: split-bf16 store (+bias)
    const int gr = lane >> 2;
    const int tq = lane & 3;
    const int row = m0 + wm * 16 + gr;
#pragma unroll
    for (int nt = 0; nt < 8; nt++) {
        int col = wn * 64 + nt * 8 + tq * 2;
        float2 bz = *(const float2*)(bias + col);
        uint32_t lo0, lo1;
        uint32_t hi0 = split_pack(acc[nt][0] + bz.x, acc[nt][1] + bz.y, &lo0);
        uint32_t hi1 = split_pack(acc[nt][2] + bz.x, acc[nt][3] + bz.y, &lo1);
        *(uint32_t*)(outh + row * DD + col)       = hi0;
        *(uint32_t*)(outl + row * DD + col)       = lo0;
        *(uint32_t*)(outh + (row + 8) * DD + col) = hi1;
        *(uint32_t*)(outl + (row + 8) * DD + col) = lo1;
    }
}

// =====================================================================
// Kernel 2: block-diagonal attention on tensor cores.
// grid (8, 16): x = 32-row tile, y = graph. block 128 (4 warps: 2m x 2n).
// Phase1: S = QK^T (3-pass split bf16) -> smem fp32
// Softmax: fused bias/mask, P -> smem split bf16
// Phase2: O = P V (3-pass split bf16), scale by 1/rowsum.
// =====================================================================
#define QSTR 136
#define KSTR 136
#define SSTR 260
#define PSTR 264
#define ATTN_SMEM ((2*32*QSTR + 2*64*KSTR + 2*32*PSTR) * 2 + 32*SSTR*4 + 128)

__global__ void __launch_bounds__(128) attn_mma_kernel(
    const float* __restrict__ bmat,
    const float* __restrict__ cmat,
    const int*   __restrict__ mask,
    float* __restrict__ out)
{
    extern __shared__ char smbase[];
    __nv_bfloat16* sQh = (__nv_bfloat16*)smbase;          // [32][136] hi, then lo
    __nv_bfloat16* sQl = sQh + 32 * QSTR;
    __nv_bfloat16* sKh = sQl + 32 * QSTR;                 // [64][136] hi, then lo (K, reused for V)
    __nv_bfloat16* sKl = sKh + 64 * KSTR;
    float*         sS  = (float*)(sKl + 64 * KSTR);       // [32][260] fp32 scores
    __nv_bfloat16* sPh = (__nv_bfloat16*)(sS + 32 * SSTR);// [32][264] hi, then lo
    __nv_bfloat16* sPl = sPh + 32 * PSTR;
    float*       sRinv = (float*)(sPl + 32 * PSTR);       // [32]

    const int t    = threadIdx.x;
    const int lane = t & 31;
    const int wid  = t >> 5;
    const int wm   = wid & 1;       // row half (16 rows)
    const int wn   = wid >> 1;      // col half
    const int g    = blockIdx.y;
    const int nbase = g * NPG + blockIdx.x * 32;
    const int kbase = g * NPG;

    // ---- load Q tile [32][128] hi/lo ----
    {
        int row = t >> 2, c0 = (t & 3) * 32;
#pragma unroll
        for (int i = 0; i < 4; i++) {
            *(uint4*)(sQh + row * QSTR + c0 + i * 8) =
                *(const uint4*)(g_qh + (nbase + row) * DD + c0 + i * 8);
            *(uint4*)(sQl + row * QSTR + c0 + i * 8) =
                *(const uint4*)(g_ql + (nbase + row) * DD + c0 + i * 8);
        }
    }

    const uint32_t aQh = smem_u32(sQh) +
        (uint32_t)(((wm * 16 + (lane & 15)) * QSTR + (lane >> 4) * 8) * 2);
    const uint32_t aQl = aQh + 32 * QSTR * 2;
    const uint32_t bKh = smem_u32(sKh) +
        (uint32_t)(((lane & 7) * KSTR + (lane >> 3) * 8) * 2);
    const uint32_t bKl = bKh + 64 * KSTR * 2;

    const int gr = lane >> 2;
    const int tq = lane & 3;

    // ---- Phase 1: S = Q K^T over 4 chunks of 64 keys ----
    for (int ch = 0; ch < 4; ch++) {
        __syncthreads();
        {
            int row = t >> 1, c0 = (t & 1) * 64;
#pragma unroll
            for (int i = 0; i < 8; i++) {
                *(uint4*)(sKh + row * KSTR + c0 + i * 8) =
                    *(const uint4*)(g_kh + (kbase + ch * 64 + row) * DD + c0 + i * 8);
                *(uint4*)(sKl + row * KSTR + c0 + i * 8) =
                    *(const uint4*)(g_kl + (kbase + ch * 64 + row) * DD + c0 + i * 8);
            }
        }
        __syncthreads();

        float s[4][4];
#pragma unroll
        for (int nt = 0; nt < 4; nt++)
#pragma unroll
            for (int j = 0; j < 4; j++) s[nt][j] = 0.f;

#pragma unroll
        for (int kp = 0; kp < 4; kp++) {     // k pairs: k-steps 2kp, 2kp+1 (dd dim)
            uint32_t ah0[4], ah1[4], al0[4], al1[4];
            ldsm_x4(aQh + kp * 64,      ah0);
            ldsm_x4(aQh + kp * 64 + 32, ah1);
            ldsm_x4(aQl + kp * 64,      al0);
            ldsm_x4(aQl + kp * 64 + 32, al1);
#pragma unroll
            for (int nt = 0; nt < 4; nt++) {
                uint32_t bofs = (uint32_t)((wn * 32 + nt * 8) * KSTR * 2) + kp * 64;
                uint32_t bh[4], bl[4];
                ldsm_x4(bKh + bofs, bh);
                ldsm_x4(bKl + bofs, bl);
                mma_bf16(s[nt], ah0, bh);
                mma_bf16(s[nt], ah0, bl);
                mma_bf16(s[nt], al0, bh);
                mma_bf16(s[nt], ah1, bh + 2);
                mma_bf16(s[nt], ah1, bl + 2);
                mma_bf16(s[nt], al1, bh + 2);
            }
        }

        // write S fragments to smem
#pragma unroll
        for (int nt = 0; nt < 4; nt++) {
            int col = ch * 64 + wn * 32 + nt * 8 + tq * 2;
            int r0 = wm * 16 + gr;
            *(float2*)(sS + r0 * SSTR + col)       = make_float2(s[nt][0], s[nt][1]);
            *(float2*)(sS + (r0 + 8) * SSTR + col) = make_float2(s[nt][2], s[nt][3]);
        }
    }

    __syncthreads();

    // ---- bias + mask + softmax; P -> split bf16 ----
    {
        const int row = t >> 2, seg = t & 3;
        const int grow = nbase + row;
        const int base = grow * NN + kbase + seg * 64;
        float* srow = sS + row * SSTR + seg * 64;

        float mx = -1e30f;
#pragma unroll 8
        for (int i = 0; i < 64; i++) {
            float v = (mask[base + i] != 0)
                          ? (srow[i] * RSCALE + bmat[base + i] + cmat[base + i])
                          : -1e30f;
            srow[i] = v;
            mx = fmaxf(mx, v);
        }
        mx = fmaxf(mx, __shfl_xor_sync(0xffffffffu, mx, 1));
        mx = fmaxf(mx, __shfl_xor_sync(0xffffffffu, mx, 2));

        float sum = 0.f;
        __nv_bfloat16* ph = sPh + row * PSTR + seg * 64;
        __nv_bfloat16* pl = sPl + row * PSTR + seg * 64;
#pragma unroll 4
        for (int i = 0; i < 64; i += 2) {
            float e0 = __expf(srow[i]     - mx);
            float e1 = __expf(srow[i + 1] - mx);
            sum += e0 + e1;
            uint32_t lo;
            uint32_t hi = split_pack(e0, e1, &lo);
            *(uint32_t*)(ph + i) = hi;
            *(uint32_t*)(pl + i) = lo;
        }
        sum += __shfl_xor_sync(0xffffffffu, sum, 1);
        sum += __shfl_xor_sync(0xffffffffu, sum, 2);
        if (seg == 0) sRinv[row] = 1.0f / sum;
    }

    // ---- Phase 2: O = P V over 4 chunks of 64 keys ----
    float o[8][4];
#pragma unroll
    for (int nt = 0; nt < 8; nt++)
#pragma unroll
        for (int j = 0; j < 4; j++) o[nt][j] = 0.f;

    const uint32_t aPh = smem_u32(sPh) +
        (uint32_t)(((wm * 16 + (lane & 15)) * PSTR + (lane >> 4) * 8) * 2);
    const uint32_t aPl = aPh + 32 * PSTR * 2;
    // V B-fragment via ldmatrix.trans on [k][n] tiles:
    // lanes 0-7: k rows 0-7 @ n+0 | 8-15: k+8 @ n+0 | 16-23: k 0-7 @ n+8 | 24-31: k+8 @ n+8
    const uint32_t bVh = smem_u32(sKh) +
        (uint32_t)((((lane & 7) + (lane & 8)) * KSTR + wn * 64 + ((lane >> 4) & 1) * 8) * 2);
    const uint32_t bVl = bVh + 64 * KSTR * 2;

    for (int ch = 0; ch < 4; ch++) {
        __syncthreads();
        {
            int row = t >> 1, c0 = (t & 1) * 64;
#pragma unroll
            for (int i = 0; i < 8; i++) {
                *(uint4*)(sKh + row * KSTR + c0 + i * 8) =
                    *(const uint4*)(g_vh + (kbase + ch * 64 + row) * DD + c0 + i * 8);
                *(uint4*)(sKl + row * KSTR + c0 + i * 8) =
                    *(const uint4*)(g_vl + (kbase + ch * 64 + row) * DD + c0 + i * 8);
            }
        }
        __syncthreads();

#pragma unroll
        for (int kt = 0; kt < 4; kt++) {    // 16-key steps within chunk
            uint32_t ph[4], pl[4];
            ldsm_x4(aPh + (ch * 64 + kt * 16) * 2, ph);
            ldsm_x4(aPl + (ch * 64 + kt * 16) * 2, pl);
#pragma unroll
            for (int np = 0; np < 4; np++) {  // pairs of 8-col n-tiles
                uint32_t vofs = (uint32_t)(kt * 16 * KSTR * 2) + np * 32;
                uint32_t vh[4], vl[4];
                ldsm_x4_t(bVh + vofs, vh);
                ldsm_x4_t(bVl + vofs, vl);
                mma_bf16(o[np * 2],     ph, vh);
                mma_bf16(o[np * 2],     ph, vl);
                mma_bf16(o[np * 2],     pl, vh);
                mma_bf16(o[np * 2 + 1], ph, vh + 2);
                mma_bf16(o[np * 2 + 1], ph, vl + 2);
                mma_bf16(o[np * 2 + 1], pl, vh + 2);
            }
        }
    }

    // ---- epilogue: normalize, store ----
    float r0inv = sRinv[wm * 16 + gr];
    float r1inv = sRinv[wm * 16 + gr + 8];
    int row0 = nbase + wm * 16 + gr;
#pragma unroll
    for (int nt = 0; nt < 8; nt++) {
        int col = wn * 64 + nt * 8 + tq * 2;
        *(float2*)(out + row0 * DD + col) =
            make_float2(o[nt][0] * r0inv, o[nt][1] * r0inv);
        *(float2*)(out + (row0 + 8) * DD + col) =
            make_float2(o[nt][2] * r1inv, o[nt][3] * r1inv);
    }
}

// =====================================================================
extern "C" void kernel_launch(void* const* d_in, const int* in_sizes, int n_in,
                              void* d_out, int out_size)
{
    const float* x    = (const float*)d_in[0];
    const float* bmat = (const float*)d_in[1];
    const float* cmat = (const float*)d_in[2];
    // d_in[3] = ptr (uniform graph layout: NPG = 256; unused)
    const int*   mask = (const int*)d_in[4];
    const float* Wq   = (const float*)d_in[5];
    const float* bq   = (const float*)d_in[6];
    const float* Wk   = (const float*)d_in[7];
    const float* bk   = (const float*)d_in[8];
    const float* Wv   = (const float*)d_in[9];
    const float* bv   = (const float*)d_in[10];
    float* out = (float*)d_out;

    cudaFuncSetAttribute(attn_mma_kernel, cudaFuncAttributeMaxDynamicSharedMemorySize,
                         ATTN_SMEM);

    convert_x_kernel<<<(NN * DIN / 4) / 256, 256>>>(x);
    convert_w_kernel<<<(3 * DD * DIN / 4) / 256, 256>>>(Wq, Wk, Wv);
    qkv_mma_kernel<<<dim3(128, 3), 128>>>(bq, bk, bv);
    attn_mma_kernel<<<dim3(8, 16), 128, ATTN_SMEM>>>(bmat, cmat, mask, out);
}